// round 1
// baseline (speedup 1.0000x reference)
#include <cuda_runtime.h>
#include <math.h>

// Problem constants (fixed by the reference)
#define NN   50000   // nodes
#define MM   5000    // hyperedges
#define HIDW 256     // max feature width of intermediates
#define CCLS 40      // classes

// ---------------- static scratch (no allocation allowed) ----------------
__device__ float d_AGG[NN * HIDW];
__device__ float d_H1 [NN * HIDW];
__device__ float d_H2 [NN * HIDW];
__device__ float d_G1 [NN * HIDW];
__device__ float d_G2 [NN * HIDW];
__device__ float d_XT [NN * HIDW];
__device__ float d_EF [MM * HIDW];
__device__ float d_SIMPLE[NN * CCLS];
__device__ float d_SDINV[NN];
__device__ float d_BINV [MM];
__device__ float d_DNINV[NN];

// ---------------- degree counting ----------------
__global__ void count_k(const int* __restrict__ idx, int n, float* __restrict__ out) {
    int i = blockIdx.x * blockDim.x + threadIdx.x;
    if (i < n) atomicAdd(&out[idx[i]], 1.0f);
}

// mode 0: d = 1/max(d,1)   (SAGE mean)
// mode 1: d = d>0 ? 1/d : 0
__global__ void recip_k(float* __restrict__ d, int n, int mode) {
    int i = blockIdx.x * blockDim.x + threadIdx.x;
    if (i >= n) return;
    float v = d[i];
    d[i] = (mode == 0) ? (1.0f / fmaxf(v, 1.0f)) : (v > 0.0f ? 1.0f / v : 0.0f);
}

// ---------------- gather + atomic scatter-add (float4 per thread) ----------------
// out[sidx[e]*F + f] += in[gidx[e]*F + f] * (gscale ? gscale[gidx[e]] : 1)
__global__ void scatter_k(const float* __restrict__ in, const int* __restrict__ gi,
                          const int* __restrict__ si, const float* __restrict__ gscale,
                          float* __restrict__ out, unsigned nE, unsigned F4) {
    unsigned t = blockIdx.x * blockDim.x + threadIdx.x;
    unsigned total = nE * F4;
    if (t >= total) return;
    unsigned e  = t / F4;
    unsigned f4 = t - e * F4;
    int g = gi[e];
    int s = si[e];
    float4 v = reinterpret_cast<const float4*>(in)[(size_t)g * F4 + f4];
    float sc = gscale ? gscale[g] : 1.0f;
    float* o = out + (size_t)s * (F4 * 4) + f4 * 4;
    atomicAdd(o + 0, v.x * sc);
    atomicAdd(o + 1, v.y * sc);
    atomicAdd(o + 2, v.z * sc);
    atomicAdd(o + 3, v.w * sc);
}

// ---------------- dual-input GEMM ----------------
// C[m,n] = sum_k (A1[m,k]*rs1[m]) * W1[n,k]  (+ sum_k A2[m,k]*W2[n,k]) (+ bias[n]) (relu?)
// A row-major [Nr,K]; W row-major [O,K] (PyTorch-style weight, used as W^T)
#define BM 128
#define BN 64
#define BK 16

__global__ __launch_bounds__(256) void gemm_dual_k(
    const float* __restrict__ A1, const float* __restrict__ rs1, const float* __restrict__ W1,
    const float* __restrict__ A2, const float* __restrict__ W2,
    const float* __restrict__ bias, float* __restrict__ C,
    int Nr, int K, int O, int relu)
{
    __shared__ float As[BK][BM + 4];
    __shared__ float Bs[BK][BN + 4];
    const int bm = blockIdx.y * BM;
    const int bn = blockIdx.x * BN;
    const int tid = threadIdx.x;
    const int tx = tid & 15;   // column group
    const int ty = tid >> 4;   // row group

    float acc[8][4];
#pragma unroll
    for (int i = 0; i < 8; i++)
#pragma unroll
        for (int j = 0; j < 4; j++) acc[i][j] = 0.0f;

    for (int pass = 0; pass < 2; pass++) {
        const float* A  = pass ? A2 : A1;
        if (!A) break;
        const float* W  = pass ? W2 : W1;
        const float* rs = pass ? nullptr : rs1;

        for (int k0 = 0; k0 < K; k0 += BK) {
            // A tile: 128x16 = 512 float4, 2 per thread
#pragma unroll
            for (int l = 0; l < 2; l++) {
                int e4 = tid + l * 256;
                int m  = e4 >> 2;
                int k4 = e4 & 3;
                int gm = bm + m;
                float4 v = make_float4(0.f, 0.f, 0.f, 0.f);
                if (gm < Nr) {
                    v = *reinterpret_cast<const float4*>(&A[(size_t)gm * K + k0 + k4 * 4]);
                    if (rs) { float s = rs[gm]; v.x *= s; v.y *= s; v.z *= s; v.w *= s; }
                }
                As[k4 * 4 + 0][m] = v.x;
                As[k4 * 4 + 1][m] = v.y;
                As[k4 * 4 + 2][m] = v.z;
                As[k4 * 4 + 3][m] = v.w;
            }
            // W tile: 64x16 = 256 float4, 1 per thread
            {
                int n  = tid >> 2;
                int k4 = tid & 3;
                int gn = bn + n;
                float4 v = make_float4(0.f, 0.f, 0.f, 0.f);
                if (gn < O)
                    v = *reinterpret_cast<const float4*>(&W[(size_t)gn * K + k0 + k4 * 4]);
                Bs[k4 * 4 + 0][n] = v.x;
                Bs[k4 * 4 + 1][n] = v.y;
                Bs[k4 * 4 + 2][n] = v.z;
                Bs[k4 * 4 + 3][n] = v.w;
            }
            __syncthreads();
#pragma unroll
            for (int k = 0; k < BK; k++) {
                float a[8], b[4];
#pragma unroll
                for (int i = 0; i < 8; i++) a[i] = As[k][ty * 8 + i];
#pragma unroll
                for (int j = 0; j < 4; j++) b[j] = Bs[k][tx * 4 + j];
#pragma unroll
                for (int i = 0; i < 8; i++)
#pragma unroll
                    for (int j = 0; j < 4; j++) acc[i][j] += a[i] * b[j];
            }
            __syncthreads();
        }
    }

#pragma unroll
    for (int i = 0; i < 8; i++) {
        int m = bm + ty * 8 + i;
        if (m >= Nr) continue;
#pragma unroll
        for (int j = 0; j < 4; j++) {
            int n = bn + tx * 4 + j;
            if (n >= O) continue;
            float v = acc[i][j];
            if (bias) v += bias[n];
            if (relu) v = fmaxf(v, 0.0f);
            C[(size_t)m * O + n] = v;
        }
    }
}

// ---------------- hyper epilogue: io = (io * dinv[row] + b[col]) [relu] ----------------
__global__ void epi_k(float* __restrict__ io, const float* __restrict__ dinv,
                      const float* __restrict__ b, int n, int F, int relu) {
    int t = blockIdx.x * blockDim.x + threadIdx.x;
    if (t >= n * F) return;
    int row = t / F;
    int col = t - row * F;
    float v = io[t] * dinv[row] + b[col];
    io[t] = relu ? fmaxf(v, 0.0f) : v;
}

// ---------------- final: logits = [S,H] @ lpw^T + lpb ; log_softmax ----------------
__global__ void final_k(const float* __restrict__ S, const float* __restrict__ Hy,
                        const float* __restrict__ lpw, const float* __restrict__ lpb,
                        float* __restrict__ out, int n) {
    __shared__ float w[CCLS * 2 * CCLS];
    __shared__ float bb[CCLS];
    for (int i = threadIdx.x; i < CCLS * 2 * CCLS; i += blockDim.x) w[i] = lpw[i];
    for (int i = threadIdx.x; i < CCLS; i += blockDim.x) bb[i] = lpb[i];
    __syncthreads();
    int node = blockIdx.x * blockDim.x + threadIdx.x;
    if (node >= n) return;

    float sv[CCLS], hv[CCLS];
#pragma unroll
    for (int k = 0; k < CCLS; k++) {
        sv[k] = S [node * CCLS + k];
        hv[k] = Hy[node * CCLS + k];
    }
    float logits[CCLS];
#pragma unroll 4
    for (int c = 0; c < CCLS; c++) {
        float acc = bb[c];
        const float* wr = &w[c * 2 * CCLS];
#pragma unroll
        for (int k = 0; k < CCLS; k++) acc += sv[k] * wr[k];
#pragma unroll
        for (int k = 0; k < CCLS; k++) acc += hv[k] * wr[CCLS + k];
        logits[c] = acc;
    }
    float mx = -1e30f;
#pragma unroll
    for (int c = 0; c < CCLS; c++) mx = fmaxf(mx, logits[c]);
    float sum = 0.0f;
#pragma unroll
    for (int c = 0; c < CCLS; c++) sum += __expf(logits[c] - mx);
    float lse = mx + logf(sum);
#pragma unroll
    for (int c = 0; c < CCLS; c++) out[node * CCLS + c] = logits[c] - lse;
}

// =======================================================================
extern "C" void kernel_launch(void* const* d_in, const int* in_sizes, int n_in,
                              void* d_out, int out_size) {
    const float* x       = (const float*)d_in[0];
    const int*   src     = (const int*)  d_in[1];
    const int*   dst     = (const int*)  d_in[2];
    const int*   he_node = (const int*)  d_in[3];
    const int*   he_edge = (const int*)  d_in[4];
    const float* s0wl = (const float*)d_in[5],  *s0wr = (const float*)d_in[6],  *s0b = (const float*)d_in[7];
    const float* s1wl = (const float*)d_in[8],  *s1wr = (const float*)d_in[9],  *s1b = (const float*)d_in[10];
    const float* s2wl = (const float*)d_in[11], *s2wr = (const float*)d_in[12], *s2b = (const float*)d_in[13];
    const float* h0w = (const float*)d_in[14], *h0b = (const float*)d_in[15];
    const float* h1w = (const float*)d_in[16], *h1b = (const float*)d_in[17];
    const float* h2w = (const float*)d_in[18], *h2b = (const float*)d_in[19];
    const float* h3w = (const float*)d_in[20], *h3b = (const float*)d_in[21];
    const float* h4w = (const float*)d_in[22], *h4b = (const float*)d_in[23];
    const float* lpw = (const float*)d_in[24], *lpb = (const float*)d_in[25];

    const int E   = in_sizes[1];
    const int ENH = in_sizes[3];
    const int FIN = in_sizes[0] / NN;   // 128

    float *AGG, *H1, *H2, *G1, *G2, *XT, *EF, *SIMPLE, *SDINV, *BINV, *DNINV;
    cudaGetSymbolAddress((void**)&AGG,    d_AGG);
    cudaGetSymbolAddress((void**)&H1,     d_H1);
    cudaGetSymbolAddress((void**)&H2,     d_H2);
    cudaGetSymbolAddress((void**)&G1,     d_G1);
    cudaGetSymbolAddress((void**)&G2,     d_G2);
    cudaGetSymbolAddress((void**)&XT,     d_XT);
    cudaGetSymbolAddress((void**)&EF,     d_EF);
    cudaGetSymbolAddress((void**)&SIMPLE, d_SIMPLE);
    cudaGetSymbolAddress((void**)&SDINV,  d_SDINV);
    cudaGetSymbolAddress((void**)&BINV,   d_BINV);
    cudaGetSymbolAddress((void**)&DNINV,  d_DNINV);

    const int TB = 256;
    auto cdiv = [](int a, int b) { return (a + b - 1) / b; };

    // -------- degrees --------
    cudaMemsetAsync(SDINV, 0, NN * sizeof(float));
    cudaMemsetAsync(BINV,  0, MM * sizeof(float));
    cudaMemsetAsync(DNINV, 0, NN * sizeof(float));
    count_k<<<cdiv(E, TB), TB>>>(dst, E, SDINV);
    count_k<<<cdiv(ENH, TB), TB>>>(he_edge, ENH, BINV);
    count_k<<<cdiv(ENH, TB), TB>>>(he_node, ENH, DNINV);
    recip_k<<<cdiv(NN, TB), TB>>>(SDINV, NN, 0);
    recip_k<<<cdiv(MM, TB), TB>>>(BINV,  MM, 1);
    recip_k<<<cdiv(NN, TB), TB>>>(DNINV, NN, 1);

    dim3 gemm_blk(256);
    auto gemm_grid = [&](int O) { return dim3((unsigned)((O + BN - 1) / BN),
                                              (unsigned)((NN + BM - 1) / BM)); };

    // -------- SAGE branch --------
    // L0: x(128) -> H1(256), relu
    cudaMemsetAsync(AGG, 0, (size_t)NN * FIN * sizeof(float));
    {
        unsigned F4 = FIN / 4, total = (unsigned)E * F4;
        scatter_k<<<cdiv(total, TB), TB>>>(x, src, dst, nullptr, AGG, E, F4);
    }
    gemm_dual_k<<<gemm_grid(HIDW), gemm_blk>>>(AGG, SDINV, s0wl, x, s0wr, s0b, H1, NN, FIN, HIDW, 1);

    // L1: H1 -> H2, relu
    cudaMemsetAsync(AGG, 0, (size_t)NN * HIDW * sizeof(float));
    {
        unsigned F4 = HIDW / 4, total = (unsigned)E * F4;
        scatter_k<<<cdiv(total, TB), TB>>>(H1, src, dst, nullptr, AGG, E, F4);
    }
    gemm_dual_k<<<gemm_grid(HIDW), gemm_blk>>>(AGG, SDINV, s1wl, H1, s1wr, s1b, H2, NN, HIDW, HIDW, 1);

    // L2: H2 -> SIMPLE(40), no relu
    cudaMemsetAsync(AGG, 0, (size_t)NN * HIDW * sizeof(float));
    {
        unsigned F4 = HIDW / 4, total = (unsigned)E * F4;
        scatter_k<<<cdiv(total, TB), TB>>>(H2, src, dst, nullptr, AGG, E, F4);
    }
    gemm_dual_k<<<gemm_grid(CCLS), gemm_blk>>>(AGG, SDINV, s2wl, H2, s2wr, s2b, SIMPLE, NN, HIDW, CCLS, 0);

    // -------- Hypergraph branch --------
    auto hyper_layer = [&](const float* gin, int K, int O, const float* w, const float* b,
                           float* gout, int relu) {
        gemm_dual_k<<<gemm_grid(O), gemm_blk>>>(gin, nullptr, w, nullptr, nullptr, nullptr, XT, NN, K, O, 0);
        unsigned F4 = O / 4;
        cudaMemsetAsync(EF, 0, (size_t)MM * O * sizeof(float));
        {
            unsigned total = (unsigned)ENH * F4;
            scatter_k<<<cdiv(total, TB), TB>>>(XT, he_node, he_edge, nullptr, EF, ENH, F4);
        }
        cudaMemsetAsync(gout, 0, (size_t)NN * O * sizeof(float));
        {
            unsigned total = (unsigned)ENH * F4;
            scatter_k<<<cdiv(total, TB), TB>>>(EF, he_edge, he_node, BINV, gout, ENH, F4);
        }
        epi_k<<<cdiv(NN * O, TB), TB>>>(gout, DNINV, b, NN, O, relu);
    };

    hyper_layer(x,  FIN,  HIDW, h0w, h0b, G1, 1);
    hyper_layer(G1, HIDW, HIDW, h1w, h1b, G2, 1);
    hyper_layer(G2, HIDW, HIDW, h2w, h2b, G1, 1);
    hyper_layer(G1, HIDW, HIDW, h3w, h3b, G2, 1);
    hyper_layer(G2, HIDW, CCLS, h4w, h4b, G1, 0);   // G1 (width 40) = x_hyper

    // -------- final linear + log_softmax --------
    final_k<<<cdiv(NN, 128), 128>>>(SIMPLE, G1, lpw, lpb, (float*)d_out, NN);
}

// round 2
// speedup vs baseline: 1.7311x; 1.7311x over previous
#include <cuda_runtime.h>
#include <math.h>

// Problem constants (fixed by the reference)
#define NN   50000   // nodes
#define MM   5000    // hyperedges
#define HIDW 256     // max feature width of intermediates
#define CCLS 40      // classes

// ---------------- static scratch (no allocation allowed) ----------------
__device__ float d_AGG[NN * HIDW];
__device__ float d_H1 [NN * HIDW];
__device__ float d_H2 [NN * HIDW];
__device__ float d_G1 [NN * HIDW];
__device__ float d_G2 [NN * HIDW];
__device__ float d_XT [NN * HIDW];
__device__ float d_EF [MM * HIDW];
__device__ float d_SIMPLE[NN * CCLS];
__device__ float d_SDINV[NN];
__device__ float d_BINV [MM];
__device__ float d_DNINV[NN];

// ---------------- degree counting ----------------
__global__ void count_k(const int* __restrict__ idx, int n, float* __restrict__ out) {
    int i = blockIdx.x * blockDim.x + threadIdx.x;
    if (i < n) atomicAdd(&out[idx[i]], 1.0f);
}

// mode 0: d = 1/max(d,1)   (SAGE mean)
// mode 1: d = d>0 ? 1/d : 0
__global__ void recip_k(float* __restrict__ d, int n, int mode) {
    int i = blockIdx.x * blockDim.x + threadIdx.x;
    if (i >= n) return;
    float v = d[i];
    d[i] = (mode == 0) ? (1.0f / fmaxf(v, 1.0f)) : (v > 0.0f ? 1.0f / v : 0.0f);
}

// ---------------- gather + vectorized reduce scatter-add ----------------
// out[sidx[e]*F + f] += in[gidx[e]*F + f] * (gscale ? gscale[gidx[e]] : 1)
// One red.global.add.v4.f32 per thread (4x fewer atomic instructions than scalar).
__global__ void scatter_k(const float* __restrict__ in, const int* __restrict__ gi,
                          const int* __restrict__ si, const float* __restrict__ gscale,
                          float* __restrict__ out, unsigned nE, unsigned F4) {
    unsigned t = blockIdx.x * blockDim.x + threadIdx.x;
    unsigned total = nE * F4;
    if (t >= total) return;
    unsigned e  = t / F4;
    unsigned f4 = t - e * F4;
    int g = gi[e];
    int s = si[e];
    float4 v = reinterpret_cast<const float4*>(in)[(size_t)g * F4 + f4];
    float sc = gscale ? gscale[g] : 1.0f;
    float* o = out + (size_t)s * (F4 * 4) + f4 * 4;
    asm volatile("red.global.add.v4.f32 [%0], {%1, %2, %3, %4};"
                 :: "l"(o), "f"(v.x * sc), "f"(v.y * sc), "f"(v.z * sc), "f"(v.w * sc)
                 : "memory");
}

// ---------------- dual-input GEMM with optional additive scattered term ----
// C[m,n] = sum_k (A1[m,k]*rs1[m]) * W1[n,k]
//        (+ sum_k A2[m,k]*W2[n,k]) (+ addin[m,n]*rs1[m]) (+ bias[n]) (relu?)
// A row-major [Nr,K]; W row-major [O,K] (PyTorch-style weight, used as W^T)
#define BM 128
#define BN 64
#define BK 16

__global__ __launch_bounds__(256) void gemm_dual_k(
    const float* __restrict__ A1, const float* __restrict__ rs1, const float* __restrict__ W1,
    const float* __restrict__ A2, const float* __restrict__ W2,
    const float* __restrict__ addin,
    const float* __restrict__ bias, float* __restrict__ C,
    int Nr, int K, int O, int relu)
{
    __shared__ float As[BK][BM + 4];
    __shared__ float Bs[BK][BN + 4];
    const int bm = blockIdx.y * BM;
    const int bn = blockIdx.x * BN;
    const int tid = threadIdx.x;
    const int tx = tid & 15;   // column group
    const int ty = tid >> 4;   // row group

    float acc[8][4];
#pragma unroll
    for (int i = 0; i < 8; i++)
#pragma unroll
        for (int j = 0; j < 4; j++) acc[i][j] = 0.0f;

    for (int pass = 0; pass < 2; pass++) {
        const float* A  = pass ? A2 : A1;
        if (!A) continue;
        const float* W  = pass ? W2 : W1;
        const float* rs = pass ? nullptr : rs1;

        for (int k0 = 0; k0 < K; k0 += BK) {
            // A tile: 128x16 = 512 float4, 2 per thread
#pragma unroll
            for (int l = 0; l < 2; l++) {
                int e4 = tid + l * 256;
                int m  = e4 >> 2;
                int k4 = e4 & 3;
                int gm = bm + m;
                float4 v = make_float4(0.f, 0.f, 0.f, 0.f);
                if (gm < Nr) {
                    v = *reinterpret_cast<const float4*>(&A[(size_t)gm * K + k0 + k4 * 4]);
                    if (rs) { float s = rs[gm]; v.x *= s; v.y *= s; v.z *= s; v.w *= s; }
                }
                As[k4 * 4 + 0][m] = v.x;
                As[k4 * 4 + 1][m] = v.y;
                As[k4 * 4 + 2][m] = v.z;
                As[k4 * 4 + 3][m] = v.w;
            }
            // W tile: 64x16 = 256 float4, 1 per thread
            {
                int n  = tid >> 2;
                int k4 = tid & 3;
                int gn = bn + n;
                float4 v = make_float4(0.f, 0.f, 0.f, 0.f);
                if (gn < O)
                    v = *reinterpret_cast<const float4*>(&W[(size_t)gn * K + k0 + k4 * 4]);
                Bs[k4 * 4 + 0][n] = v.x;
                Bs[k4 * 4 + 1][n] = v.y;
                Bs[k4 * 4 + 2][n] = v.z;
                Bs[k4 * 4 + 3][n] = v.w;
            }
            __syncthreads();
#pragma unroll
            for (int k = 0; k < BK; k++) {
                float a[8], b[4];
#pragma unroll
                for (int i = 0; i < 8; i++) a[i] = As[k][ty * 8 + i];
#pragma unroll
                for (int j = 0; j < 4; j++) b[j] = Bs[k][tx * 4 + j];
#pragma unroll
                for (int i = 0; i < 8; i++)
#pragma unroll
                    for (int j = 0; j < 4; j++) acc[i][j] += a[i] * b[j];
            }
            __syncthreads();
        }
    }

#pragma unroll
    for (int i = 0; i < 8; i++) {
        int m = bm + ty * 8 + i;
        if (m >= Nr) continue;
        float rsm = (addin && rs1) ? rs1[m] : 1.0f;
#pragma unroll
        for (int j = 0; j < 4; j++) {
            int n = bn + tx * 4 + j;
            if (n >= O) continue;
            float v = acc[i][j];
            if (addin) v += addin[(size_t)m * O + n] * rsm;
            if (bias) v += bias[n];
            if (relu) v = fmaxf(v, 0.0f);
            C[(size_t)m * O + n] = v;
        }
    }
}

// ---------------- hyper epilogue: io = (io * dinv[row] + b[col]) [relu] ----------------
__global__ void epi_k(float* __restrict__ io, const float* __restrict__ dinv,
                      const float* __restrict__ b, int n, int F, int relu) {
    int t = blockIdx.x * blockDim.x + threadIdx.x;
    if (t >= n * F) return;
    int row = t / F;
    int col = t - row * F;
    float v = io[t] * dinv[row] + b[col];
    io[t] = relu ? fmaxf(v, 0.0f) : v;
}

// ---------------- final: logits = [S,H] @ lpw^T + lpb ; log_softmax ----------------
__global__ void final_k(const float* __restrict__ S, const float* __restrict__ Hy,
                        const float* __restrict__ lpw, const float* __restrict__ lpb,
                        float* __restrict__ out, int n) {
    __shared__ float w[CCLS * 2 * CCLS];
    __shared__ float bb[CCLS];
    for (int i = threadIdx.x; i < CCLS * 2 * CCLS; i += blockDim.x) w[i] = lpw[i];
    for (int i = threadIdx.x; i < CCLS; i += blockDim.x) bb[i] = lpb[i];
    __syncthreads();
    int node = blockIdx.x * blockDim.x + threadIdx.x;
    if (node >= n) return;

    float sv[CCLS], hv[CCLS];
#pragma unroll
    for (int k = 0; k < CCLS; k++) {
        sv[k] = S [node * CCLS + k];
        hv[k] = Hy[node * CCLS + k];
    }
    float logits[CCLS];
#pragma unroll 4
    for (int c = 0; c < CCLS; c++) {
        float acc = bb[c];
        const float* wr = &w[c * 2 * CCLS];
#pragma unroll
        for (int k = 0; k < CCLS; k++) acc += sv[k] * wr[k];
#pragma unroll
        for (int k = 0; k < CCLS; k++) acc += hv[k] * wr[CCLS + k];
        logits[c] = acc;
    }
    float mx = -1e30f;
#pragma unroll
    for (int c = 0; c < CCLS; c++) mx = fmaxf(mx, logits[c]);
    float sum = 0.0f;
#pragma unroll
    for (int c = 0; c < CCLS; c++) sum += __expf(logits[c] - mx);
    float lse = mx + logf(sum);
#pragma unroll
    for (int c = 0; c < CCLS; c++) out[node * CCLS + c] = logits[c] - lse;
}

// =======================================================================
extern "C" void kernel_launch(void* const* d_in, const int* in_sizes, int n_in,
                              void* d_out, int out_size) {
    const float* x       = (const float*)d_in[0];
    const int*   src     = (const int*)  d_in[1];
    const int*   dst     = (const int*)  d_in[2];
    const int*   he_node = (const int*)  d_in[3];
    const int*   he_edge = (const int*)  d_in[4];
    const float* s0wl = (const float*)d_in[5],  *s0wr = (const float*)d_in[6],  *s0b = (const float*)d_in[7];
    const float* s1wl = (const float*)d_in[8],  *s1wr = (const float*)d_in[9],  *s1b = (const float*)d_in[10];
    const float* s2wl = (const float*)d_in[11], *s2wr = (const float*)d_in[12], *s2b = (const float*)d_in[13];
    const float* h0w = (const float*)d_in[14], *h0b = (const float*)d_in[15];
    const float* h1w = (const float*)d_in[16], *h1b = (const float*)d_in[17];
    const float* h2w = (const float*)d_in[18], *h2b = (const float*)d_in[19];
    const float* h3w = (const float*)d_in[20], *h3b = (const float*)d_in[21];
    const float* h4w = (const float*)d_in[22], *h4b = (const float*)d_in[23];
    const float* lpw = (const float*)d_in[24], *lpb = (const float*)d_in[25];

    const int E   = in_sizes[1];
    const int ENH = in_sizes[3];
    const int FIN = in_sizes[0] / NN;   // 128

    float *AGG, *H1, *H2, *G1, *G2, *XT, *EF, *SIMPLE, *SDINV, *BINV, *DNINV;
    cudaGetSymbolAddress((void**)&AGG,    d_AGG);
    cudaGetSymbolAddress((void**)&H1,     d_H1);
    cudaGetSymbolAddress((void**)&H2,     d_H2);
    cudaGetSymbolAddress((void**)&G1,     d_G1);
    cudaGetSymbolAddress((void**)&G2,     d_G2);
    cudaGetSymbolAddress((void**)&XT,     d_XT);
    cudaGetSymbolAddress((void**)&EF,     d_EF);
    cudaGetSymbolAddress((void**)&SIMPLE, d_SIMPLE);
    cudaGetSymbolAddress((void**)&SDINV,  d_SDINV);
    cudaGetSymbolAddress((void**)&BINV,   d_BINV);
    cudaGetSymbolAddress((void**)&DNINV,  d_DNINV);

    const int TB = 256;
    auto cdiv = [](int a, int b) { return (a + b - 1) / b; };

    // -------- degrees --------
    cudaMemsetAsync(SDINV, 0, NN * sizeof(float));
    cudaMemsetAsync(BINV,  0, MM * sizeof(float));
    cudaMemsetAsync(DNINV, 0, NN * sizeof(float));
    count_k<<<cdiv(E, TB), TB>>>(dst, E, SDINV);
    count_k<<<cdiv(ENH, TB), TB>>>(he_edge, ENH, BINV);
    count_k<<<cdiv(ENH, TB), TB>>>(he_node, ENH, DNINV);
    recip_k<<<cdiv(NN, TB), TB>>>(SDINV, NN, 0);
    recip_k<<<cdiv(MM, TB), TB>>>(BINV,  MM, 1);
    recip_k<<<cdiv(NN, TB), TB>>>(DNINV, NN, 1);

    dim3 gemm_blk(256);
    auto gemm_grid = [&](int O) { return dim3((unsigned)((O + BN - 1) / BN),
                                              (unsigned)((NN + BM - 1) / BM)); };

    // -------- SAGE branch --------
    // L0: x(128) -> H1(256), relu  (scatter the narrower input side: 128-wide)
    cudaMemsetAsync(AGG, 0, (size_t)NN * FIN * sizeof(float));
    {
        unsigned F4 = FIN / 4, total = (unsigned)E * F4;
        scatter_k<<<cdiv(total, TB), TB>>>(x, src, dst, nullptr, AGG, E, F4);
    }
    gemm_dual_k<<<gemm_grid(HIDW), gemm_blk>>>(AGG, SDINV, s0wl, x, s0wr, nullptr, s0b, H1, NN, FIN, HIDW, 1);

    // L1: H1 -> H2, relu (256 -> 256, no narrower side)
    cudaMemsetAsync(AGG, 0, (size_t)NN * HIDW * sizeof(float));
    {
        unsigned F4 = HIDW / 4, total = (unsigned)E * F4;
        scatter_k<<<cdiv(total, TB), TB>>>(H1, src, dst, nullptr, AGG, E, F4);
    }
    gemm_dual_k<<<gemm_grid(HIDW), gemm_blk>>>(AGG, SDINV, s1wl, H1, s1wr, nullptr, s1b, H2, NN, HIDW, HIDW, 1);

    // L2: H2 -> SIMPLE(40), no relu. Transform FIRST (linearity of segment mean):
    //   seg_mean(H2[src]) @ wl^T == seg_sum((H2 @ wl^T)[src]) * dinv
    // XT = H2 @ s2wl^T  (40-wide), scatter 40-wide, combine in GEMM epilogue.
    gemm_dual_k<<<gemm_grid(CCLS), gemm_blk>>>(H2, nullptr, s2wl, nullptr, nullptr, nullptr, nullptr, XT, NN, HIDW, CCLS, 0);
    cudaMemsetAsync(AGG, 0, (size_t)NN * CCLS * sizeof(float));
    {
        unsigned F4 = CCLS / 4, total = (unsigned)E * F4;
        scatter_k<<<cdiv(total, TB), TB>>>(XT, src, dst, nullptr, AGG, E, F4);
    }
    // SIMPLE = H2 @ s2wr^T + AGG * sdinv + b
    gemm_dual_k<<<gemm_grid(CCLS), gemm_blk>>>(nullptr, SDINV, nullptr, H2, s2wr, AGG, s2b, SIMPLE, NN, HIDW, CCLS, 0);

    // -------- Hypergraph branch --------
    auto hyper_layer = [&](const float* gin, int K, int O, const float* w, const float* b,
                           float* gout, int relu) {
        gemm_dual_k<<<gemm_grid(O), gemm_blk>>>(gin, nullptr, w, nullptr, nullptr, nullptr, nullptr, XT, NN, K, O, 0);
        unsigned F4 = O / 4;
        cudaMemsetAsync(EF, 0, (size_t)MM * O * sizeof(float));
        {
            unsigned total = (unsigned)ENH * F4;
            scatter_k<<<cdiv(total, TB), TB>>>(XT, he_node, he_edge, nullptr, EF, ENH, F4);
        }
        cudaMemsetAsync(gout, 0, (size_t)NN * O * sizeof(float));
        {
            unsigned total = (unsigned)ENH * F4;
            scatter_k<<<cdiv(total, TB), TB>>>(EF, he_edge, he_node, BINV, gout, ENH, F4);
        }
        epi_k<<<cdiv(NN * O, TB), TB>>>(gout, DNINV, b, NN, O, relu);
    };

    hyper_layer(x,  FIN,  HIDW, h0w, h0b, G1, 1);
    hyper_layer(G1, HIDW, HIDW, h1w, h1b, G2, 1);
    hyper_layer(G2, HIDW, HIDW, h2w, h2b, G1, 1);
    hyper_layer(G1, HIDW, HIDW, h3w, h3b, G2, 1);
    hyper_layer(G2, HIDW, CCLS, h4w, h4b, G1, 0);   // G1 (width 40) = x_hyper

    // -------- final linear + log_softmax --------
    final_k<<<cdiv(NN, 128), 128>>>(SIMPLE, G1, lpw, lpb, (float*)d_out, NN);
}

// round 3
// speedup vs baseline: 2.1323x; 1.2318x over previous
#include <cuda_runtime.h>
#include <mma.h>
#include <math.h>

using namespace nvcuda;

// Problem constants (fixed by the reference)
#define NN   50000   // nodes
#define MM   5000    // hyperedges
#define HIDW 256     // max feature width of intermediates
#define CCLS 40      // classes

// ---------------- static scratch (no allocation allowed) ----------------
__device__ float d_AGG[NN * HIDW];
__device__ float d_H1 [NN * HIDW];
__device__ float d_H2 [NN * HIDW];
__device__ float d_G1 [NN * HIDW];
__device__ float d_G2 [NN * HIDW];
__device__ float d_XT [NN * HIDW];
__device__ float d_EF [MM * HIDW];
__device__ float d_SIMPLE[NN * CCLS];
__device__ float d_SDINV[NN];
__device__ float d_BINV [MM];
__device__ float d_DNINV[NN];

// ---------------- degree counting ----------------
__global__ void count_k(const int* __restrict__ idx, int n, float* __restrict__ out) {
    int i = blockIdx.x * blockDim.x + threadIdx.x;
    if (i < n) atomicAdd(&out[idx[i]], 1.0f);
}

// mode 0: d = 1/max(d,1)   (SAGE mean)
// mode 1: d = d>0 ? 1/d : 0
__global__ void recip_k(float* __restrict__ d, int n, int mode) {
    int i = blockIdx.x * blockDim.x + threadIdx.x;
    if (i >= n) return;
    float v = d[i];
    d[i] = (mode == 0) ? (1.0f / fmaxf(v, 1.0f)) : (v > 0.0f ? 1.0f / v : 0.0f);
}

// ---------------- gather + vectorized reduce scatter-add ----------------
// out[sidx[e]*F + f] += in[gidx[e]*F + f] * (gscale ? gscale[gidx[e]] : 1)
__global__ void scatter_k(const float* __restrict__ in, const int* __restrict__ gi,
                          const int* __restrict__ si, const float* __restrict__ gscale,
                          float* __restrict__ out, unsigned nE, unsigned F4) {
    unsigned t = blockIdx.x * blockDim.x + threadIdx.x;
    unsigned total = nE * F4;
    if (t >= total) return;
    unsigned e  = t / F4;
    unsigned f4 = t - e * F4;
    int g = gi[e];
    int s = si[e];
    float4 v = reinterpret_cast<const float4*>(in)[(size_t)g * F4 + f4];
    float sc = gscale ? gscale[g] : 1.0f;
    float* o = out + (size_t)s * (F4 * 4) + f4 * 4;
    asm volatile("red.global.add.v4.f32 [%0], {%1, %2, %3, %4};"
                 :: "l"(o), "f"(v.x * sc), "f"(v.y * sc), "f"(v.z * sc), "f"(v.w * sc)
                 : "memory");
}

// ---------------- TF32 tensor-core dual GEMM ----------------
// C[m,n] = sum_k (A1[m,k]*rs1[m]) * W1[n,k]
//        (+ sum_k A2[m,k]*W2[n,k]) (+ addin[m,n]*rs1[m]) (+ bias[n]) (relu?)
// A row-major [Nr,K]; W row-major [O,K] (used as B col-major k x n with ld=K)
#define BM 128
#define BN 64
#define BK 16
#define CLD 36   // per-warp C patch leading dim (multiple of 4 floats)

__global__ __launch_bounds__(256) void gemm_tc_k(
    const float* __restrict__ A1, const float* __restrict__ rs1, const float* __restrict__ W1,
    const float* __restrict__ A2, const float* __restrict__ W2,
    const float* __restrict__ addin,
    const float* __restrict__ bias, float* __restrict__ C,
    int Nr, int K, int O, int relu)
{
    __shared__ union {
        struct {
            float As[BM][BK + 4];   // m-major, 16B-aligned rows (20 floats = 80B)
            float Bs[BN][BK + 4];   // n-major
        } t;
        float Cs[8][32 * CLD];      // per-warp 32x32 output patch
    } sm;

    const int bm  = blockIdx.y * BM;
    const int bn  = blockIdx.x * BN;
    const int tid = threadIdx.x;
    const int wid = tid >> 5;
    const int lane = tid & 31;
    const int warpM = (wid >> 1) * 32;   // 4 warp rows
    const int warpN = (wid & 1) * 32;    // 2 warp cols

    wmma::fragment<wmma::accumulator, 16, 16, 8, float> acc[2][2];
#pragma unroll
    for (int i = 0; i < 2; i++)
#pragma unroll
        for (int j = 0; j < 2; j++) wmma::fill_fragment(acc[i][j], 0.0f);

    for (int pass = 0; pass < 2; pass++) {
        const float* A  = pass ? A2 : A1;
        if (!A) continue;
        const float* W  = pass ? W2 : W1;
        const float* rs = pass ? nullptr : rs1;

        for (int k0 = 0; k0 < K; k0 += BK) {
            // A tile: 128 rows x 16 k = 512 float4, 2 per thread
#pragma unroll
            for (int l = 0; l < 2; l++) {
                int e4 = tid + l * 256;
                int m  = e4 >> 2;
                int k4 = e4 & 3;
                int gm = bm + m;
                float4 v = make_float4(0.f, 0.f, 0.f, 0.f);
                if (gm < Nr) {
                    v = *reinterpret_cast<const float4*>(&A[(size_t)gm * K + k0 + k4 * 4]);
                    if (rs) { float s = rs[gm]; v.x *= s; v.y *= s; v.z *= s; v.w *= s; }
                }
                *reinterpret_cast<float4*>(&sm.t.As[m][k4 * 4]) = v;
            }
            // W tile: 64 rows x 16 k = 256 float4, 1 per thread
            {
                int n  = tid >> 2;
                int k4 = tid & 3;
                int gn = bn + n;
                float4 v = make_float4(0.f, 0.f, 0.f, 0.f);
                if (gn < O)
                    v = *reinterpret_cast<const float4*>(&W[(size_t)gn * K + k0 + k4 * 4]);
                *reinterpret_cast<float4*>(&sm.t.Bs[n][k4 * 4]) = v;
            }
            __syncthreads();

#pragma unroll
            for (int kk = 0; kk < BK; kk += 8) {
                wmma::fragment<wmma::matrix_a, 16, 16, 8, wmma::precision::tf32, wmma::row_major> af[2];
                wmma::fragment<wmma::matrix_b, 16, 16, 8, wmma::precision::tf32, wmma::col_major> bf[2];
#pragma unroll
                for (int i = 0; i < 2; i++) {
                    wmma::load_matrix_sync(af[i], &sm.t.As[warpM + i * 16][kk], BK + 4);
#pragma unroll
                    for (int t = 0; t < af[i].num_elements; t++)
                        af[i].x[t] = wmma::__float_to_tf32(af[i].x[t]);
                }
#pragma unroll
                for (int j = 0; j < 2; j++) {
                    wmma::load_matrix_sync(bf[j], &sm.t.Bs[warpN + j * 16][kk], BK + 4);
#pragma unroll
                    for (int t = 0; t < bf[j].num_elements; t++)
                        bf[j].x[t] = wmma::__float_to_tf32(bf[j].x[t]);
                }
#pragma unroll
                for (int i = 0; i < 2; i++)
#pragma unroll
                    for (int j = 0; j < 2; j++)
                        wmma::mma_sync(acc[i][j], af[i], bf[j], acc[i][j]);
            }
            __syncthreads();
        }
    }

    // Epilogue: park frags in smem (aliased), then predicated global writes
#pragma unroll
    for (int i = 0; i < 2; i++)
#pragma unroll
        for (int j = 0; j < 2; j++)
            wmma::store_matrix_sync(&sm.Cs[wid][(i * 16) * CLD + j * 16], acc[i][j],
                                    CLD, wmma::mem_row_major);
    __syncwarp();

    for (int idx = lane; idx < 32 * 32; idx += 32) {
        int r = idx >> 5;
        int c = idx & 31;
        int m = bm + warpM + r;
        int n = bn + warpN + c;
        if (m >= Nr || n >= O) continue;
        float v = sm.Cs[wid][r * CLD + c];
        if (addin) v += addin[(size_t)m * O + n] * (rs1 ? rs1[m] : 1.0f);
        if (bias)  v += bias[n];
        if (relu)  v = fmaxf(v, 0.0f);
        C[(size_t)m * O + n] = v;
    }
}

// ---------------- hyper epilogue: io = (io * dinv[row] + b[col]) [relu] ----------------
__global__ void epi_k(float* __restrict__ io, const float* __restrict__ dinv,
                      const float* __restrict__ b, int n, int F, int relu) {
    int t = blockIdx.x * blockDim.x + threadIdx.x;
    if (t >= n * F) return;
    int row = t / F;
    int col = t - row * F;
    float v = io[t] * dinv[row] + b[col];
    io[t] = relu ? fmaxf(v, 0.0f) : v;
}

// ---------------- final: logits = [S,H] @ lpw^T + lpb ; log_softmax ----------------
__global__ void final_k(const float* __restrict__ S, const float* __restrict__ Hy,
                        const float* __restrict__ lpw, const float* __restrict__ lpb,
                        float* __restrict__ out, int n) {
    __shared__ float w[CCLS * 2 * CCLS];
    __shared__ float bb[CCLS];
    for (int i = threadIdx.x; i < CCLS * 2 * CCLS; i += blockDim.x) w[i] = lpw[i];
    for (int i = threadIdx.x; i < CCLS; i += blockDim.x) bb[i] = lpb[i];
    __syncthreads();
    int node = blockIdx.x * blockDim.x + threadIdx.x;
    if (node >= n) return;

    float sv[CCLS], hv[CCLS];
#pragma unroll
    for (int k = 0; k < CCLS; k++) {
        sv[k] = S [node * CCLS + k];
        hv[k] = Hy[node * CCLS + k];
    }
    float logits[CCLS];
#pragma unroll 4
    for (int c = 0; c < CCLS; c++) {
        float acc = bb[c];
        const float* wr = &w[c * 2 * CCLS];
#pragma unroll
        for (int k = 0; k < CCLS; k++) acc += sv[k] * wr[k];
#pragma unroll
        for (int k = 0; k < CCLS; k++) acc += hv[k] * wr[CCLS + k];
        logits[c] = acc;
    }
    float mx = -1e30f;
#pragma unroll
    for (int c = 0; c < CCLS; c++) mx = fmaxf(mx, logits[c]);
    float sum = 0.0f;
#pragma unroll
    for (int c = 0; c < CCLS; c++) sum += __expf(logits[c] - mx);
    float lse = mx + logf(sum);
#pragma unroll
    for (int c = 0; c < CCLS; c++) out[node * CCLS + c] = logits[c] - lse;
}

// =======================================================================
extern "C" void kernel_launch(void* const* d_in, const int* in_sizes, int n_in,
                              void* d_out, int out_size) {
    const float* x       = (const float*)d_in[0];
    const int*   src     = (const int*)  d_in[1];
    const int*   dst     = (const int*)  d_in[2];
    const int*   he_node = (const int*)  d_in[3];
    const int*   he_edge = (const int*)  d_in[4];
    const float* s0wl = (const float*)d_in[5],  *s0wr = (const float*)d_in[6],  *s0b = (const float*)d_in[7];
    const float* s1wl = (const float*)d_in[8],  *s1wr = (const float*)d_in[9],  *s1b = (const float*)d_in[10];
    const float* s2wl = (const float*)d_in[11], *s2wr = (const float*)d_in[12], *s2b = (const float*)d_in[13];
    const float* h0w = (const float*)d_in[14], *h0b = (const float*)d_in[15];
    const float* h1w = (const float*)d_in[16], *h1b = (const float*)d_in[17];
    const float* h2w = (const float*)d_in[18], *h2b = (const float*)d_in[19];
    const float* h3w = (const float*)d_in[20], *h3b = (const float*)d_in[21];
    const float* h4w = (const float*)d_in[22], *h4b = (const float*)d_in[23];
    const float* lpw = (const float*)d_in[24], *lpb = (const float*)d_in[25];

    const int E   = in_sizes[1];
    const int ENH = in_sizes[3];
    const int FIN = in_sizes[0] / NN;   // 128

    float *AGG, *H1, *H2, *G1, *G2, *XT, *EF, *SIMPLE, *SDINV, *BINV, *DNINV;
    cudaGetSymbolAddress((void**)&AGG,    d_AGG);
    cudaGetSymbolAddress((void**)&H1,     d_H1);
    cudaGetSymbolAddress((void**)&H2,     d_H2);
    cudaGetSymbolAddress((void**)&G1,     d_G1);
    cudaGetSymbolAddress((void**)&G2,     d_G2);
    cudaGetSymbolAddress((void**)&XT,     d_XT);
    cudaGetSymbolAddress((void**)&EF,     d_EF);
    cudaGetSymbolAddress((void**)&SIMPLE, d_SIMPLE);
    cudaGetSymbolAddress((void**)&SDINV,  d_SDINV);
    cudaGetSymbolAddress((void**)&BINV,   d_BINV);
    cudaGetSymbolAddress((void**)&DNINV,  d_DNINV);

    const int TB = 256;
    auto cdiv = [](int a, int b) { return (a + b - 1) / b; };

    // -------- degrees --------
    cudaMemsetAsync(SDINV, 0, NN * sizeof(float));
    cudaMemsetAsync(BINV,  0, MM * sizeof(float));
    cudaMemsetAsync(DNINV, 0, NN * sizeof(float));
    count_k<<<cdiv(E, TB), TB>>>(dst, E, SDINV);
    count_k<<<cdiv(ENH, TB), TB>>>(he_edge, ENH, BINV);
    count_k<<<cdiv(ENH, TB), TB>>>(he_node, ENH, DNINV);
    recip_k<<<cdiv(NN, TB), TB>>>(SDINV, NN, 0);
    recip_k<<<cdiv(MM, TB), TB>>>(BINV,  MM, 1);
    recip_k<<<cdiv(NN, TB), TB>>>(DNINV, NN, 1);

    dim3 gemm_blk(256);
    auto gemm_grid = [&](int O) { return dim3((unsigned)((O + BN - 1) / BN),
                                              (unsigned)((NN + BM - 1) / BM)); };

    // -------- SAGE branch --------
    // L0: aggregate x at width 128, dual-GEMM (agg*wl + x*wr) -> H1(256), relu
    cudaMemsetAsync(AGG, 0, (size_t)NN * FIN * sizeof(float));
    {
        unsigned F4 = FIN / 4, total = (unsigned)E * F4;
        scatter_k<<<cdiv(total, TB), TB>>>(x, src, dst, nullptr, AGG, E, F4);
    }
    gemm_tc_k<<<gemm_grid(HIDW), gemm_blk>>>(AGG, SDINV, s0wl, x, s0wr, nullptr, s0b, H1, NN, FIN, HIDW, 1);

    // L1: H1 -> H2, relu (256 -> 256)
    cudaMemsetAsync(AGG, 0, (size_t)NN * HIDW * sizeof(float));
    {
        unsigned F4 = HIDW / 4, total = (unsigned)E * F4;
        scatter_k<<<cdiv(total, TB), TB>>>(H1, src, dst, nullptr, AGG, E, F4);
    }
    gemm_tc_k<<<gemm_grid(HIDW), gemm_blk>>>(AGG, SDINV, s1wl, H1, s1wr, nullptr, s1b, H2, NN, HIDW, HIDW, 1);

    // L2: transform first to width 40, scatter narrow, combine in epilogue
    gemm_tc_k<<<gemm_grid(CCLS), gemm_blk>>>(H2, nullptr, s2wl, nullptr, nullptr, nullptr, nullptr, XT, NN, HIDW, CCLS, 0);
    cudaMemsetAsync(AGG, 0, (size_t)NN * CCLS * sizeof(float));
    {
        unsigned F4 = CCLS / 4, total = (unsigned)E * F4;
        scatter_k<<<cdiv(total, TB), TB>>>(XT, src, dst, nullptr, AGG, E, F4);
    }
    gemm_tc_k<<<gemm_grid(CCLS), gemm_blk>>>(nullptr, SDINV, nullptr, H2, s2wr, AGG, s2b, SIMPLE, NN, HIDW, CCLS, 0);

    // -------- Hypergraph branch --------
    // L0 aggregate-first at width 128 (operator commutes with linear transform):
    //   G1 = relu( (Dinv H Binv H^T x) @ h0w^T + h0b )
    {
        unsigned F4 = FIN / 4;
        cudaMemsetAsync(EF, 0, (size_t)MM * FIN * sizeof(float));
        {
            unsigned total = (unsigned)ENH * F4;
            scatter_k<<<cdiv(total, TB), TB>>>(x, he_node, he_edge, nullptr, EF, ENH, F4);
        }
        cudaMemsetAsync(XT, 0, (size_t)NN * FIN * sizeof(float));
        {
            unsigned total = (unsigned)ENH * F4;
            scatter_k<<<cdiv(total, TB), TB>>>(EF, he_edge, he_node, BINV, XT, ENH, F4);
        }
        // rs1 = DNINV applied to aggregated rows during A load; bias + relu fused
        gemm_tc_k<<<gemm_grid(HIDW), gemm_blk>>>(XT, DNINV, h0w, nullptr, nullptr, nullptr, h0b, G1, NN, FIN, HIDW, 1);
    }

    // Layers 1..4: transform-first
    auto hyper_layer = [&](const float* gin, int K, int O, const float* w, const float* b,
                           float* gout, int relu) {
        gemm_tc_k<<<gemm_grid(O), gemm_blk>>>(gin, nullptr, w, nullptr, nullptr, nullptr, nullptr, XT, NN, K, O, 0);
        unsigned F4 = O / 4;
        cudaMemsetAsync(EF, 0, (size_t)MM * O * sizeof(float));
        {
            unsigned total = (unsigned)ENH * F4;
            scatter_k<<<cdiv(total, TB), TB>>>(XT, he_node, he_edge, nullptr, EF, ENH, F4);
        }
        cudaMemsetAsync(gout, 0, (size_t)NN * O * sizeof(float));
        {
            unsigned total = (unsigned)ENH * F4;
            scatter_k<<<cdiv(total, TB), TB>>>(EF, he_edge, he_node, BINV, gout, ENH, F4);
        }
        epi_k<<<cdiv(NN * O, TB), TB>>>(gout, DNINV, b, NN, O, relu);
    };

    hyper_layer(G1, HIDW, HIDW, h1w, h1b, G2, 1);
    hyper_layer(G2, HIDW, HIDW, h2w, h2b, G1, 1);
    hyper_layer(G1, HIDW, HIDW, h3w, h3b, G2, 1);
    hyper_layer(G2, HIDW, CCLS, h4w, h4b, G1, 0);   // G1 (width 40) = x_hyper

    // -------- final linear + log_softmax --------
    final_k<<<cdiv(NN, 128), 128>>>(SIMPLE, G1, lpw, lpb, (float*)d_out, NN);
}

// round 4
// speedup vs baseline: 2.4395x; 1.1441x over previous
#include <cuda_runtime.h>
#include <mma.h>
#include <math.h>

using namespace nvcuda;

#define NN   50000
#define MM   5000
#define HIDW 256
#define CCLS 40

// ---------------- static scratch ----------------
__device__ float d_AGG[NN * HIDW];
__device__ float d_H1 [NN * HIDW];
__device__ float d_H2 [NN * HIDW];
__device__ float d_G1 [NN * HIDW];
__device__ float d_G2 [NN * HIDW];
__device__ float d_XT [NN * HIDW];
__device__ float d_EF [MM * HIDW];
__device__ float d_EF2[MM * HIDW];
__device__ float d_SIMPLE[NN * CCLS];
__device__ float d_SDINV[NN];
__device__ float d_BINV [MM];
__device__ float d_DNINV[NN];

// ---------------- degree counting ----------------
__global__ void count_k(const int* __restrict__ idx, int n, float* __restrict__ out) {
    int i = blockIdx.x * blockDim.x + threadIdx.x;
    if (i < n) atomicAdd(&out[idx[i]], 1.0f);
}

__global__ void recip_k(float* __restrict__ d, int n, int mode) {
    int i = blockIdx.x * blockDim.x + threadIdx.x;
    if (i >= n) return;
    float v = d[i];
    d[i] = (mode == 0) ? (1.0f / fmaxf(v, 1.0f)) : (v > 0.0f ? 1.0f / v : 0.0f);
}

// ---------------- row scale: io[row][:] *= s[row] (float4) ----------------
__global__ void rowscale_k(float* __restrict__ io, const float* __restrict__ s,
                           unsigned n, unsigned F4) {
    unsigned t = blockIdx.x * blockDim.x + threadIdx.x;
    if (t >= n * F4) return;
    unsigned row = t / F4;
    float sc = s[row];
    float4 v = reinterpret_cast<float4*>(io)[t];
    v.x *= sc; v.y *= sc; v.z *= sc; v.w *= sc;
    reinterpret_cast<float4*>(io)[t] = v;
}

// ---------------- gather + vectorized reduce scatter-add ----------------
__global__ void scatter_k(const float* __restrict__ in, const int* __restrict__ gi,
                          const int* __restrict__ si, const float* __restrict__ gscale,
                          float* __restrict__ out, unsigned nE, unsigned F4) {
    unsigned t = blockIdx.x * blockDim.x + threadIdx.x;
    unsigned total = nE * F4;
    if (t >= total) return;
    unsigned e  = t / F4;
    unsigned f4 = t - e * F4;
    int g = gi[e];
    int s = si[e];
    float4 v = reinterpret_cast<const float4*>(in)[(size_t)g * F4 + f4];
    float sc = gscale ? gscale[g] : 1.0f;
    float* o = out + (size_t)s * (F4 * 4) + f4 * 4;
    asm volatile("red.global.add.v4.f32 [%0], {%1, %2, %3, %4};"
                 :: "l"(o), "f"(v.x * sc), "f"(v.y * sc), "f"(v.z * sc), "f"(v.w * sc)
                 : "memory");
}

// ---------------- TF32 tensor-core dual GEMM, cp.async double-buffered ----
// C[m,n] = sum_k A1[m,k]*W1[n,k] (+ sum_k A2[m,k]*W2[n,k]) (+ addin[m,n]) (+ bias[n]) (relu?)
// A row-major [Nr,K]; W row-major [O,K]
#define BM 128
#define BN 64
#define BK 32
#define LDK 36   // BK + 4 padding (floats)
#define CLD 36

__global__ __launch_bounds__(256) void gemm_tc_k(
    const float* __restrict__ A1, const float* __restrict__ W1,
    const float* __restrict__ A2, const float* __restrict__ W2,
    const float* __restrict__ addin, const float* __restrict__ bias,
    float* __restrict__ C, int Nr, int K, int O, int relu)
{
    __shared__ union {
        struct {
            float As[2][BM][LDK];
            float Bs[2][BN][LDK];
        } t;
        float Cs[8][32 * CLD];
    } sm;

    const int bm   = blockIdx.y * BM;
    const int bn   = blockIdx.x * BN;
    const int tid  = threadIdx.x;
    const int wid  = tid >> 5;
    const int lane = tid & 31;
    const int warpM = (wid >> 1) * 32;
    const int warpN = (wid & 1) * 32;

    const int KT = K / BK;
    const int npass = A2 ? 2 : 1;
    const int T = KT * npass;

    auto issue = [&](int t, int buf) {
        int p  = t / KT;
        int k0 = (t - p * KT) * BK;
        const float* A = p ? A2 : A1;
        const float* W = p ? W2 : W1;
        // A tile: 128 rows x 8 float4 = 1024, 4 per thread
#pragma unroll
        for (int l = 0; l < 4; l++) {
            int e = tid + l * 256;
            int row = e >> 3, c4 = e & 7;
            int gm = min(bm + row, Nr - 1);
            const float* src = A + (size_t)gm * K + k0 + c4 * 4;
            unsigned dst = (unsigned)__cvta_generic_to_shared(&sm.t.As[buf][row][c4 * 4]);
            asm volatile("cp.async.cg.shared.global [%0], [%1], 16;" :: "r"(dst), "l"(src));
        }
        // B tile: 64 rows x 8 float4 = 512, 2 per thread
#pragma unroll
        for (int l = 0; l < 2; l++) {
            int e = tid + l * 256;
            int row = e >> 3, c4 = e & 7;
            int gn = min(bn + row, O - 1);
            const float* src = W + (size_t)gn * K + k0 + c4 * 4;
            unsigned dst = (unsigned)__cvta_generic_to_shared(&sm.t.Bs[buf][row][c4 * 4]);
            asm volatile("cp.async.cg.shared.global [%0], [%1], 16;" :: "r"(dst), "l"(src));
        }
        asm volatile("cp.async.commit_group;");
    };

    wmma::fragment<wmma::accumulator, 16, 16, 8, float> acc[2][2];
#pragma unroll
    for (int i = 0; i < 2; i++)
#pragma unroll
        for (int j = 0; j < 2; j++) wmma::fill_fragment(acc[i][j], 0.0f);

    issue(0, 0);
    for (int t = 0; t < T; t++) {
        int buf = t & 1;
        if (t + 1 < T) {
            issue(t + 1, buf ^ 1);
            asm volatile("cp.async.wait_group 1;");
        } else {
            asm volatile("cp.async.wait_group 0;");
        }
        __syncthreads();

#pragma unroll
        for (int kk = 0; kk < BK; kk += 8) {
            wmma::fragment<wmma::matrix_a, 16, 16, 8, wmma::precision::tf32, wmma::row_major> af[2];
            wmma::fragment<wmma::matrix_b, 16, 16, 8, wmma::precision::tf32, wmma::col_major> bf[2];
#pragma unroll
            for (int i = 0; i < 2; i++) {
                wmma::load_matrix_sync(af[i], &sm.t.As[buf][warpM + i * 16][kk], LDK);
#pragma unroll
                for (int q = 0; q < af[i].num_elements; q++)
                    af[i].x[q] = wmma::__float_to_tf32(af[i].x[q]);
            }
#pragma unroll
            for (int j = 0; j < 2; j++) {
                wmma::load_matrix_sync(bf[j], &sm.t.Bs[buf][warpN + j * 16][kk], LDK);
#pragma unroll
                for (int q = 0; q < bf[j].num_elements; q++)
                    bf[j].x[q] = wmma::__float_to_tf32(bf[j].x[q]);
            }
#pragma unroll
            for (int i = 0; i < 2; i++)
#pragma unroll
                for (int j = 0; j < 2; j++)
                    wmma::mma_sync(acc[i][j], af[i], bf[j], acc[i][j]);
        }
        __syncthreads();
    }

    // epilogue via aliased smem patch
#pragma unroll
    for (int i = 0; i < 2; i++)
#pragma unroll
        for (int j = 0; j < 2; j++)
            wmma::store_matrix_sync(&sm.Cs[wid][(i * 16) * CLD + j * 16], acc[i][j],
                                    CLD, wmma::mem_row_major);
    __syncwarp();

    for (int idx = lane; idx < 32 * 32; idx += 32) {
        int r = idx >> 5;
        int c = idx & 31;
        int m = bm + warpM + r;
        int n = bn + warpN + c;
        if (m >= Nr || n >= O) continue;
        float v = sm.Cs[wid][r * CLD + c];
        if (addin) v += addin[(size_t)m * O + n];
        if (bias)  v += bias[n];
        if (relu)  v = fmaxf(v, 0.0f);
        C[(size_t)m * O + n] = v;
    }
}

// ---------------- hyper epilogue ----------------
__global__ void epi_k(float* __restrict__ io, const float* __restrict__ dinv,
                      const float* __restrict__ b, int n, int F, int relu) {
    int t = blockIdx.x * blockDim.x + threadIdx.x;
    if (t >= n * F) return;
    int row = t / F;
    int col = t - row * F;
    float v = io[t] * dinv[row] + b[col];
    io[t] = relu ? fmaxf(v, 0.0f) : v;
}

// ---------------- final: logits + log_softmax ----------------
__global__ void final_k(const float* __restrict__ S, const float* __restrict__ Hy,
                        const float* __restrict__ lpw, const float* __restrict__ lpb,
                        float* __restrict__ out, int n) {
    __shared__ float w[CCLS * 2 * CCLS];
    __shared__ float bb[CCLS];
    for (int i = threadIdx.x; i < CCLS * 2 * CCLS; i += blockDim.x) w[i] = lpw[i];
    for (int i = threadIdx.x; i < CCLS; i += blockDim.x) bb[i] = lpb[i];
    __syncthreads();
    int node = blockIdx.x * blockDim.x + threadIdx.x;
    if (node >= n) return;

    float sv[CCLS], hv[CCLS];
#pragma unroll
    for (int k = 0; k < CCLS; k++) {
        sv[k] = S [node * CCLS + k];
        hv[k] = Hy[node * CCLS + k];
    }
    float logits[CCLS];
#pragma unroll 4
    for (int c = 0; c < CCLS; c++) {
        float acc = bb[c];
        const float* wr = &w[c * 2 * CCLS];
#pragma unroll
        for (int k = 0; k < CCLS; k++) acc += sv[k] * wr[k];
#pragma unroll
        for (int k = 0; k < CCLS; k++) acc += hv[k] * wr[CCLS + k];
        logits[c] = acc;
    }
    float mx = -1e30f;
#pragma unroll
    for (int c = 0; c < CCLS; c++) mx = fmaxf(mx, logits[c]);
    float sum = 0.0f;
#pragma unroll
    for (int c = 0; c < CCLS; c++) sum += __expf(logits[c] - mx);
    float lse = mx + logf(sum);
#pragma unroll
    for (int c = 0; c < CCLS; c++) out[node * CCLS + c] = logits[c] - lse;
}

// =======================================================================
extern "C" void kernel_launch(void* const* d_in, const int* in_sizes, int n_in,
                              void* d_out, int out_size) {
    const float* x       = (const float*)d_in[0];
    const int*   src     = (const int*)  d_in[1];
    const int*   dst     = (const int*)  d_in[2];
    const int*   he_node = (const int*)  d_in[3];
    const int*   he_edge = (const int*)  d_in[4];
    const float* s0wl = (const float*)d_in[5],  *s0wr = (const float*)d_in[6],  *s0b = (const float*)d_in[7];
    const float* s1wl = (const float*)d_in[8],  *s1wr = (const float*)d_in[9],  *s1b = (const float*)d_in[10];
    const float* s2wl = (const float*)d_in[11], *s2wr = (const float*)d_in[12], *s2b = (const float*)d_in[13];
    const float* h0w = (const float*)d_in[14], *h0b = (const float*)d_in[15];
    const float* h1w = (const float*)d_in[16], *h1b = (const float*)d_in[17];
    const float* h2w = (const float*)d_in[18], *h2b = (const float*)d_in[19];
    const float* h3w = (const float*)d_in[20], *h3b = (const float*)d_in[21];
    const float* h4w = (const float*)d_in[22], *h4b = (const float*)d_in[23];
    const float* lpw = (const float*)d_in[24], *lpb = (const float*)d_in[25];

    const int E   = in_sizes[1];
    const int ENH = in_sizes[3];
    const int FIN = in_sizes[0] / NN;   // 128

    float *AGG, *H1, *H2, *G1, *G2, *XT, *EF, *EF2, *SIMPLE, *SDINV, *BINV, *DNINV;
    cudaGetSymbolAddress((void**)&AGG,    d_AGG);
    cudaGetSymbolAddress((void**)&H1,     d_H1);
    cudaGetSymbolAddress((void**)&H2,     d_H2);
    cudaGetSymbolAddress((void**)&G1,     d_G1);
    cudaGetSymbolAddress((void**)&G2,     d_G2);
    cudaGetSymbolAddress((void**)&XT,     d_XT);
    cudaGetSymbolAddress((void**)&EF,     d_EF);
    cudaGetSymbolAddress((void**)&EF2,    d_EF2);
    cudaGetSymbolAddress((void**)&SIMPLE, d_SIMPLE);
    cudaGetSymbolAddress((void**)&SDINV,  d_SDINV);
    cudaGetSymbolAddress((void**)&BINV,   d_BINV);
    cudaGetSymbolAddress((void**)&DNINV,  d_DNINV);

    const int TB = 256;
    auto cdiv = [](int a, int b) { return (a + b - 1) / b; };
    dim3 gemm_blk(256);
    auto gemm_grid = [&](int Nr, int O) {
        return dim3((unsigned)((O + BN - 1) / BN), (unsigned)((Nr + BM - 1) / BM));
    };

    // -------- memsets (not kernel launches) --------
    cudaMemsetAsync(SDINV, 0, NN * sizeof(float));
    cudaMemsetAsync(BINV,  0, MM * sizeof(float));
    cudaMemsetAsync(DNINV, 0, NN * sizeof(float));
    cudaMemsetAsync(AGG, 0, (size_t)NN * FIN * sizeof(float));

    // launch index 0..4
    count_k<<<cdiv(E, TB), TB>>>(dst, E, SDINV);
    recip_k<<<cdiv(NN, TB), TB>>>(SDINV, NN, 0);
    {
        unsigned F4 = FIN / 4, total = (unsigned)E * F4;
        scatter_k<<<cdiv(total, TB), TB>>>(x, src, dst, nullptr, AGG, E, F4);
    }
    rowscale_k<<<cdiv(NN * (FIN / 4), TB), TB>>>(AGG, SDINV, NN, FIN / 4);
    count_k<<<cdiv(ENH, TB), TB>>>(he_edge, ENH, BINV);
    // launch index 5 (ncu-profiled): SAGE L0 dual GEMM
    gemm_tc_k<<<gemm_grid(NN, HIDW), gemm_blk>>>(AGG, s0wl, x, s0wr, nullptr, s0b, H1, NN, FIN, HIDW, 1);
    recip_k<<<cdiv(MM, TB), TB>>>(BINV, MM, 1);
    count_k<<<cdiv(ENH, TB), TB>>>(he_node, ENH, DNINV);
    recip_k<<<cdiv(NN, TB), TB>>>(DNINV, NN, 1);

    // -------- SAGE L1 --------
    cudaMemsetAsync(AGG, 0, (size_t)NN * HIDW * sizeof(float));
    {
        unsigned F4 = HIDW / 4, total = (unsigned)E * F4;
        scatter_k<<<cdiv(total, TB), TB>>>(H1, src, dst, nullptr, AGG, E, F4);
    }
    rowscale_k<<<cdiv(NN * (HIDW / 4), TB), TB>>>(AGG, SDINV, NN, HIDW / 4);
    gemm_tc_k<<<gemm_grid(NN, HIDW), gemm_blk>>>(AGG, s1wl, H1, s1wr, nullptr, s1b, H2, NN, HIDW, HIDW, 1);

    // -------- SAGE L2 (transform-first to width 40) --------
    gemm_tc_k<<<gemm_grid(NN, CCLS), gemm_blk>>>(H2, s2wl, nullptr, nullptr, nullptr, nullptr, XT, NN, HIDW, CCLS, 0);
    cudaMemsetAsync(AGG, 0, (size_t)NN * CCLS * sizeof(float));
    {
        unsigned F4 = CCLS / 4, total = (unsigned)E * F4;
        scatter_k<<<cdiv(total, TB), TB>>>(XT, src, dst, nullptr, AGG, E, F4);
    }
    rowscale_k<<<cdiv(NN * (CCLS / 4), TB), TB>>>(AGG, SDINV, NN, CCLS / 4);
    gemm_tc_k<<<gemm_grid(NN, CCLS), gemm_blk>>>(H2, s2wr, nullptr, nullptr, AGG, s2b, SIMPLE, NN, HIDW, CCLS, 0);

    // -------- Hyper L0 (aggregate-first at width 128) --------
    {
        unsigned F4 = FIN / 4;
        cudaMemsetAsync(EF, 0, (size_t)MM * FIN * sizeof(float));
        {
            unsigned total = (unsigned)ENH * F4;
            scatter_k<<<cdiv(total, TB), TB>>>(x, he_node, he_edge, nullptr, EF, ENH, F4);
        }
        cudaMemsetAsync(XT, 0, (size_t)NN * FIN * sizeof(float));
        {
            unsigned total = (unsigned)ENH * F4;
            scatter_k<<<cdiv(total, TB), TB>>>(EF, he_edge, he_node, BINV, XT, ENH, F4);
        }
        rowscale_k<<<cdiv(NN * F4, TB), TB>>>(XT, DNINV, NN, F4);
        gemm_tc_k<<<gemm_grid(NN, HIDW), gemm_blk>>>(XT, h0w, nullptr, nullptr, nullptr, h0b, G1, NN, FIN, HIDW, 1);
    }

    // -------- Hyper L1..L3: hyperedge-space GEMM (5000 rows!) --------
    auto hyper_mid = [&](const float* gin, const float* w, const float* b, float* gout) {
        unsigned F4 = HIDW / 4;
        cudaMemsetAsync(EF, 0, (size_t)MM * HIDW * sizeof(float));
        {
            unsigned total = (unsigned)ENH * F4;
            scatter_k<<<cdiv(total, TB), TB>>>(gin, he_node, he_edge, nullptr, EF, ENH, F4);
        }
        rowscale_k<<<cdiv(MM * F4, TB), TB>>>(EF, BINV, MM, F4);
        gemm_tc_k<<<gemm_grid(MM, HIDW), gemm_blk>>>(EF, w, nullptr, nullptr, nullptr, nullptr, EF2, MM, HIDW, HIDW, 0);
        cudaMemsetAsync(gout, 0, (size_t)NN * HIDW * sizeof(float));
        {
            unsigned total = (unsigned)ENH * F4;
            scatter_k<<<cdiv(total, TB), TB>>>(EF2, he_edge, he_node, nullptr, gout, ENH, F4);
        }
        epi_k<<<cdiv(NN * HIDW, TB), TB>>>(gout, DNINV, b, NN, HIDW, 1);
    };
    hyper_mid(G1, h1w, h1b, G2);
    hyper_mid(G2, h2w, h2b, G1);
    hyper_mid(G1, h3w, h3b, G2);

    // -------- Hyper L4 (transform-first to width 40) --------
    {
        gemm_tc_k<<<gemm_grid(NN, CCLS), gemm_blk>>>(G2, h4w, nullptr, nullptr, nullptr, nullptr, XT, NN, HIDW, CCLS, 0);
        unsigned F4 = CCLS / 4;
        cudaMemsetAsync(EF, 0, (size_t)MM * CCLS * sizeof(float));
        {
            unsigned total = (unsigned)ENH * F4;
            scatter_k<<<cdiv(total, TB), TB>>>(XT, he_node, he_edge, nullptr, EF, ENH, F4);
        }
        cudaMemsetAsync(G1, 0, (size_t)NN * CCLS * sizeof(float));
        {
            unsigned total = (unsigned)ENH * F4;
            scatter_k<<<cdiv(total, TB), TB>>>(EF, he_edge, he_node, BINV, G1, ENH, F4);
        }
        epi_k<<<cdiv(NN * CCLS, TB), TB>>>(G1, DNINV, h4b, NN, CCLS, 0);
    }

    // -------- final --------
    final_k<<<cdiv(NN, 128), 128>>>(SIMPLE, G1, lpw, lpb, (float*)d_out, NN);
}

// round 5
// speedup vs baseline: 2.6759x; 1.0969x over previous
#include <cuda_runtime.h>
#include <mma.h>
#include <math.h>

using namespace nvcuda;

#define NN   50000
#define MM   5000
#define HIDW 256
#define CCLS 40

// ---------------- static scratch ----------------
__device__ float d_AGG[NN * HIDW];
__device__ float d_H1 [NN * HIDW];
__device__ float d_H2 [NN * HIDW];
__device__ float d_G1 [NN * HIDW];
__device__ float d_G2 [NN * HIDW];
__device__ float d_XT [NN * HIDW];
__device__ float d_HXT[NN * HIDW];
__device__ float d_EF [MM * HIDW];
__device__ float d_EF2[MM * HIDW];
__device__ float d_SIMPLE[NN * CCLS];
__device__ float d_SDINV[NN];
__device__ float d_BINV [MM];
__device__ float d_DNINV[NN];

// ---------------- degree counting ----------------
__global__ void count_k(const int* __restrict__ idx, int n, float* __restrict__ out) {
    int i = blockIdx.x * blockDim.x + threadIdx.x;
    if (i < n) atomicAdd(&out[idx[i]], 1.0f);
}

__global__ void recip_k(float* __restrict__ d, int n, int mode) {
    int i = blockIdx.x * blockDim.x + threadIdx.x;
    if (i >= n) return;
    float v = d[i];
    d[i] = (mode == 0) ? (1.0f / fmaxf(v, 1.0f)) : (v > 0.0f ? 1.0f / v : 0.0f);
}

// ---------------- fused gather/scale/scatter-add ----------------
// v = in[gi[e]][f4];  if gbias: v = relu(v + gbias[f4]);
// out[si[e]][f4] +=red v * (gscale?gscale[g]:1) * (sscale?sscale[s]:1)
__global__ void scatter_k(const float* __restrict__ in, const int* __restrict__ gi,
                          const int* __restrict__ si,
                          const float* __restrict__ gscale,
                          const float* __restrict__ sscale,
                          const float* __restrict__ gbias,
                          float* __restrict__ out, unsigned nE, unsigned F4) {
    unsigned t = blockIdx.x * blockDim.x + threadIdx.x;
    unsigned total = nE * F4;
    if (t >= total) return;
    unsigned e  = t / F4;
    unsigned f4 = t - e * F4;
    int g = gi[e];
    int s = si[e];
    float4 v = reinterpret_cast<const float4*>(in)[(size_t)g * F4 + f4];
    if (gbias) {
        float4 b = reinterpret_cast<const float4*>(gbias)[f4];
        v.x = fmaxf(v.x + b.x, 0.0f);
        v.y = fmaxf(v.y + b.y, 0.0f);
        v.z = fmaxf(v.z + b.z, 0.0f);
        v.w = fmaxf(v.w + b.w, 0.0f);
    }
    float sc = 1.0f;
    if (gscale) sc *= gscale[g];
    if (sscale) sc *= sscale[s];
    float* o = out + (size_t)s * (F4 * 4) + f4 * 4;
    asm volatile("red.global.add.v4.f32 [%0], {%1, %2, %3, %4};"
                 :: "l"(o), "f"(v.x * sc), "f"(v.y * sc), "f"(v.z * sc), "f"(v.w * sc)
                 : "memory");
}

// ---------------- TF32 tensor-core dual GEMM, cp.async double-buffered ----
#define BM 128
#define BN 64
#define BK 32
#define LDK 36
#define CLD 36

__global__ __launch_bounds__(256) void gemm_tc_k(
    const float* __restrict__ A1, const float* __restrict__ W1,
    const float* __restrict__ A2, const float* __restrict__ W2,
    const float* __restrict__ addin, const float* __restrict__ bias,
    float* __restrict__ C, int Nr, int K, int O, int relu)
{
    __shared__ union {
        struct {
            float As[2][BM][LDK];
            float Bs[2][BN][LDK];
        } t;
        float Cs[8][32 * CLD];
    } sm;

    const int bm   = blockIdx.y * BM;
    const int bn   = blockIdx.x * BN;
    const int tid  = threadIdx.x;
    const int wid  = tid >> 5;
    const int lane = tid & 31;
    const int warpM = (wid >> 1) * 32;
    const int warpN = (wid & 1) * 32;

    const int KT = K / BK;
    const int npass = A2 ? 2 : 1;
    const int T = KT * npass;

    auto issue = [&](int t, int buf) {
        int p  = t / KT;
        int k0 = (t - p * KT) * BK;
        const float* A = p ? A2 : A1;
        const float* W = p ? W2 : W1;
#pragma unroll
        for (int l = 0; l < 4; l++) {
            int e = tid + l * 256;
            int row = e >> 3, c4 = e & 7;
            int gm = min(bm + row, Nr - 1);
            const float* src = A + (size_t)gm * K + k0 + c4 * 4;
            unsigned dst = (unsigned)__cvta_generic_to_shared(&sm.t.As[buf][row][c4 * 4]);
            asm volatile("cp.async.cg.shared.global [%0], [%1], 16;" :: "r"(dst), "l"(src));
        }
#pragma unroll
        for (int l = 0; l < 2; l++) {
            int e = tid + l * 256;
            int row = e >> 3, c4 = e & 7;
            int gn = min(bn + row, O - 1);
            const float* src = W + (size_t)gn * K + k0 + c4 * 4;
            unsigned dst = (unsigned)__cvta_generic_to_shared(&sm.t.Bs[buf][row][c4 * 4]);
            asm volatile("cp.async.cg.shared.global [%0], [%1], 16;" :: "r"(dst), "l"(src));
        }
        asm volatile("cp.async.commit_group;");
    };

    wmma::fragment<wmma::accumulator, 16, 16, 8, float> acc[2][2];
#pragma unroll
    for (int i = 0; i < 2; i++)
#pragma unroll
        for (int j = 0; j < 2; j++) wmma::fill_fragment(acc[i][j], 0.0f);

    issue(0, 0);
    for (int t = 0; t < T; t++) {
        int buf = t & 1;
        if (t + 1 < T) {
            issue(t + 1, buf ^ 1);
            asm volatile("cp.async.wait_group 1;");
        } else {
            asm volatile("cp.async.wait_group 0;");
        }
        __syncthreads();

#pragma unroll
        for (int kk = 0; kk < BK; kk += 8) {
            wmma::fragment<wmma::matrix_a, 16, 16, 8, wmma::precision::tf32, wmma::row_major> af[2];
            wmma::fragment<wmma::matrix_b, 16, 16, 8, wmma::precision::tf32, wmma::col_major> bf[2];
#pragma unroll
            for (int i = 0; i < 2; i++) {
                wmma::load_matrix_sync(af[i], &sm.t.As[buf][warpM + i * 16][kk], LDK);
#pragma unroll
                for (int q = 0; q < af[i].num_elements; q++)
                    af[i].x[q] = wmma::__float_to_tf32(af[i].x[q]);
            }
#pragma unroll
            for (int j = 0; j < 2; j++) {
                wmma::load_matrix_sync(bf[j], &sm.t.Bs[buf][warpN + j * 16][kk], LDK);
#pragma unroll
                for (int q = 0; q < bf[j].num_elements; q++)
                    bf[j].x[q] = wmma::__float_to_tf32(bf[j].x[q]);
            }
#pragma unroll
            for (int i = 0; i < 2; i++)
#pragma unroll
                for (int j = 0; j < 2; j++)
                    wmma::mma_sync(acc[i][j], af[i], bf[j], acc[i][j]);
        }
        __syncthreads();
    }

#pragma unroll
    for (int i = 0; i < 2; i++)
#pragma unroll
        for (int j = 0; j < 2; j++)
            wmma::store_matrix_sync(&sm.Cs[wid][(i * 16) * CLD + j * 16], acc[i][j],
                                    CLD, wmma::mem_row_major);
    __syncwarp();

    for (int idx = lane; idx < 32 * 32; idx += 32) {
        int r = idx >> 5;
        int c = idx & 31;
        int m = bm + warpM + r;
        int n = bn + warpN + c;
        if (m >= Nr || n >= O) continue;
        float v = sm.Cs[wid][r * CLD + c];
        if (addin) v += addin[(size_t)m * O + n];
        if (bias)  v += bias[n];
        if (relu)  v = fmaxf(v, 0.0f);
        C[(size_t)m * O + n] = v;
    }
}

// ---------------- epilogue: io = relu?(io + b[col]) ----------------
__global__ void epi_k(float* __restrict__ io, const float* __restrict__ b,
                      int n, int F, int relu) {
    int t = blockIdx.x * blockDim.x + threadIdx.x;
    if (t >= n * F) return;
    int col = t % F;
    float v = io[t] + b[col];
    io[t] = relu ? fmaxf(v, 0.0f) : v;
}

// ---------------- final: logits + log_softmax (hb added to Hy) ----------------
__global__ void final_k(const float* __restrict__ S, const float* __restrict__ Hy,
                        const float* __restrict__ hb,
                        const float* __restrict__ lpw, const float* __restrict__ lpb,
                        float* __restrict__ out, int n) {
    __shared__ float w[CCLS * 2 * CCLS];
    __shared__ float bb[CCLS];
    __shared__ float hbb[CCLS];
    for (int i = threadIdx.x; i < CCLS * 2 * CCLS; i += blockDim.x) w[i] = lpw[i];
    for (int i = threadIdx.x; i < CCLS; i += blockDim.x) { bb[i] = lpb[i]; hbb[i] = hb[i]; }
    __syncthreads();
    int node = blockIdx.x * blockDim.x + threadIdx.x;
    if (node >= n) return;

    float sv[CCLS], hv[CCLS];
#pragma unroll
    for (int k = 0; k < CCLS; k++) {
        sv[k] = S [node * CCLS + k];
        hv[k] = Hy[node * CCLS + k] + hbb[k];
    }
    float logits[CCLS];
#pragma unroll 4
    for (int c = 0; c < CCLS; c++) {
        float acc = bb[c];
        const float* wr = &w[c * 2 * CCLS];
#pragma unroll
        for (int k = 0; k < CCLS; k++) acc += sv[k] * wr[k];
#pragma unroll
        for (int k = 0; k < CCLS; k++) acc += hv[k] * wr[CCLS + k];
        logits[c] = acc;
    }
    float mx = -1e30f;
#pragma unroll
    for (int c = 0; c < CCLS; c++) mx = fmaxf(mx, logits[c]);
    float sum = 0.0f;
#pragma unroll
    for (int c = 0; c < CCLS; c++) sum += __expf(logits[c] - mx);
    float lse = mx + logf(sum);
#pragma unroll
    for (int c = 0; c < CCLS; c++) out[node * CCLS + c] = logits[c] - lse;
}

// =======================================================================
extern "C" void kernel_launch(void* const* d_in, const int* in_sizes, int n_in,
                              void* d_out, int out_size) {
    const float* x       = (const float*)d_in[0];
    const int*   src     = (const int*)  d_in[1];
    const int*   dst     = (const int*)  d_in[2];
    const int*   he_node = (const int*)  d_in[3];
    const int*   he_edge = (const int*)  d_in[4];
    const float* s0wl = (const float*)d_in[5],  *s0wr = (const float*)d_in[6],  *s0b = (const float*)d_in[7];
    const float* s1wl = (const float*)d_in[8],  *s1wr = (const float*)d_in[9],  *s1b = (const float*)d_in[10];
    const float* s2wl = (const float*)d_in[11], *s2wr = (const float*)d_in[12], *s2b = (const float*)d_in[13];
    const float* h0w = (const float*)d_in[14], *h0b = (const float*)d_in[15];
    const float* h1w = (const float*)d_in[16], *h1b = (const float*)d_in[17];
    const float* h2w = (const float*)d_in[18], *h2b = (const float*)d_in[19];
    const float* h3w = (const float*)d_in[20], *h3b = (const float*)d_in[21];
    const float* h4w = (const float*)d_in[22], *h4b = (const float*)d_in[23];
    const float* lpw = (const float*)d_in[24], *lpb = (const float*)d_in[25];

    const int E   = in_sizes[1];
    const int ENH = in_sizes[3];
    const int FIN = in_sizes[0] / NN;   // 128

    float *AGG, *H1, *H2, *G1, *G2, *XT, *HXT, *EF, *EF2, *SIMPLE, *SDINV, *BINV, *DNINV;
    cudaGetSymbolAddress((void**)&AGG,    d_AGG);
    cudaGetSymbolAddress((void**)&H1,     d_H1);
    cudaGetSymbolAddress((void**)&H2,     d_H2);
    cudaGetSymbolAddress((void**)&G1,     d_G1);
    cudaGetSymbolAddress((void**)&G2,     d_G2);
    cudaGetSymbolAddress((void**)&XT,     d_XT);
    cudaGetSymbolAddress((void**)&HXT,    d_HXT);
    cudaGetSymbolAddress((void**)&EF,     d_EF);
    cudaGetSymbolAddress((void**)&EF2,    d_EF2);
    cudaGetSymbolAddress((void**)&SIMPLE, d_SIMPLE);
    cudaGetSymbolAddress((void**)&SDINV,  d_SDINV);
    cudaGetSymbolAddress((void**)&BINV,   d_BINV);
    cudaGetSymbolAddress((void**)&DNINV,  d_DNINV);

    const int TB = 256;
    auto cdiv = [](int a, int b) { return (a + b - 1) / b; };
    dim3 gemm_blk(256);
    auto gemm_grid = [&](int Nr, int O) {
        return dim3((unsigned)((O + BN - 1) / BN), (unsigned)((Nr + BM - 1) / BM));
    };

    // -------- fork: hyper branch on its own stream --------
    cudaStream_t hs;
    cudaStreamCreateWithFlags(&hs, cudaStreamNonBlocking);
    cudaEvent_t evFork, evJoin;
    cudaEventCreateWithFlags(&evFork, cudaEventDisableTiming);
    cudaEventCreateWithFlags(&evJoin, cudaEventDisableTiming);
    cudaEventRecord(evFork, 0);
    cudaStreamWaitEvent(hs, evFork, 0);

    // ======== SAGE branch (stream 0) ========
    cudaMemsetAsync(SDINV, 0, NN * sizeof(float), 0);
    cudaMemsetAsync(AGG, 0, (size_t)NN * FIN * sizeof(float), 0);
    count_k<<<cdiv(E, TB), TB, 0, 0>>>(dst, E, SDINV);
    recip_k<<<cdiv(NN, TB), TB, 0, 0>>>(SDINV, NN, 0);
    // L0: AGG = sum x[src] * sdinv[dst]; H1 = relu(AGG@wl + x@wr + b)
    {
        unsigned F4 = FIN / 4, total = (unsigned)E * F4;
        scatter_k<<<cdiv(total, TB), TB, 0, 0>>>(x, src, dst, nullptr, SDINV, nullptr, AGG, E, F4);
    }
    gemm_tc_k<<<gemm_grid(NN, HIDW), gemm_blk, 0, 0>>>(AGG, s0wl, x, s0wr, nullptr, s0b, H1, NN, FIN, HIDW, 1);
    // L1
    cudaMemsetAsync(AGG, 0, (size_t)NN * HIDW * sizeof(float), 0);
    {
        unsigned F4 = HIDW / 4, total = (unsigned)E * F4;
        scatter_k<<<cdiv(total, TB), TB, 0, 0>>>(H1, src, dst, nullptr, SDINV, nullptr, AGG, E, F4);
    }
    gemm_tc_k<<<gemm_grid(NN, HIDW), gemm_blk, 0, 0>>>(AGG, s1wl, H1, s1wr, nullptr, s1b, H2, NN, HIDW, HIDW, 1);
    // L2 transform-first to width 40
    gemm_tc_k<<<gemm_grid(NN, CCLS), gemm_blk, 0, 0>>>(H2, s2wl, nullptr, nullptr, nullptr, nullptr, XT, NN, HIDW, CCLS, 0);
    cudaMemsetAsync(AGG, 0, (size_t)NN * CCLS * sizeof(float), 0);
    {
        unsigned F4 = CCLS / 4, total = (unsigned)E * F4;
        scatter_k<<<cdiv(total, TB), TB, 0, 0>>>(XT, src, dst, nullptr, SDINV, nullptr, AGG, E, F4);
    }
    gemm_tc_k<<<gemm_grid(NN, CCLS), gemm_blk, 0, 0>>>(H2, s2wr, nullptr, nullptr, AGG, s2b, SIMPLE, NN, HIDW, CCLS, 0);

    // ======== Hypergraph branch (stream hs) ========
    cudaMemsetAsync(BINV,  0, MM * sizeof(float), hs);
    cudaMemsetAsync(DNINV, 0, NN * sizeof(float), hs);
    count_k<<<cdiv(ENH, TB), TB, 0, hs>>>(he_edge, ENH, BINV);
    count_k<<<cdiv(ENH, TB), TB, 0, hs>>>(he_node, ENH, DNINV);
    recip_k<<<cdiv(MM, TB), TB, 0, hs>>>(BINV, MM, 1);
    recip_k<<<cdiv(NN, TB), TB, 0, hs>>>(DNINV, NN, 1);

    // L0 aggregate-first at width 128: HXT = Dinv H Binv H^T x ; G1 = relu(HXT@h0w + h0b)
    {
        unsigned F4 = FIN / 4;
        cudaMemsetAsync(EF, 0, (size_t)MM * FIN * sizeof(float), hs);
        {
            unsigned total = (unsigned)ENH * F4;
            scatter_k<<<cdiv(total, TB), TB, 0, hs>>>(x, he_node, he_edge, nullptr, BINV, nullptr, EF, ENH, F4);
        }
        cudaMemsetAsync(HXT, 0, (size_t)NN * FIN * sizeof(float), hs);
        {
            unsigned total = (unsigned)ENH * F4;
            scatter_k<<<cdiv(total, TB), TB, 0, hs>>>(EF, he_edge, he_node, nullptr, DNINV, nullptr, HXT, ENH, F4);
        }
        gemm_tc_k<<<gemm_grid(NN, HIDW), gemm_blk, 0, hs>>>(HXT, h0w, nullptr, nullptr, nullptr, h0b, G1, NN, FIN, HIDW, 1);
    }

    // Mid layers 1..3: hyperedge-space GEMM (5000 rows); bias+relu of previous
    // layer folded into the gather (pb). Output carries pending bias.
    auto hyper_mid = [&](const float* gin, const float* pb, const float* w, float* gout) {
        unsigned F4 = HIDW / 4;
        cudaMemsetAsync(EF, 0, (size_t)MM * HIDW * sizeof(float), hs);
        {
            unsigned total = (unsigned)ENH * F4;
            scatter_k<<<cdiv(total, TB), TB, 0, hs>>>(gin, he_node, he_edge, nullptr, BINV, pb, EF, ENH, F4);
        }
        gemm_tc_k<<<gemm_grid(MM, HIDW), gemm_blk, 0, hs>>>(EF, w, nullptr, nullptr, nullptr, nullptr, EF2, MM, HIDW, HIDW, 0);
        cudaMemsetAsync(gout, 0, (size_t)NN * HIDW * sizeof(float), hs);
        {
            unsigned total = (unsigned)ENH * F4;
            scatter_k<<<cdiv(total, TB), TB, 0, hs>>>(EF2, he_edge, he_node, nullptr, DNINV, nullptr, gout, ENH, F4);
        }
    };
    hyper_mid(G1, nullptr, h1w, G2);  // G2 pending h1b
    hyper_mid(G2, h1b,    h2w, G1);   // G1 pending h2b
    hyper_mid(G1, h2b,    h3w, G2);   // G2 pending h3b
    // materialize bias+relu for L4's GEMM input
    epi_k<<<cdiv(NN * HIDW, TB), TB, 0, hs>>>(G2, h3b, NN, HIDW, 1);

    // L4 transform-first to width 40; h4b folded into final_k
    {
        gemm_tc_k<<<gemm_grid(NN, CCLS), gemm_blk, 0, hs>>>(G2, h4w, nullptr, nullptr, nullptr, nullptr, HXT, NN, HIDW, CCLS, 0);
        unsigned F4 = CCLS / 4;
        cudaMemsetAsync(EF, 0, (size_t)MM * CCLS * sizeof(float), hs);
        {
            unsigned total = (unsigned)ENH * F4;
            scatter_k<<<cdiv(total, TB), TB, 0, hs>>>(HXT, he_node, he_edge, nullptr, BINV, nullptr, EF, ENH, F4);
        }
        cudaMemsetAsync(G1, 0, (size_t)NN * CCLS * sizeof(float), hs);
        {
            unsigned total = (unsigned)ENH * F4;
            scatter_k<<<cdiv(total, TB), TB, 0, hs>>>(EF, he_edge, he_node, nullptr, DNINV, nullptr, G1, ENH, F4);
        }
    }

    // -------- join + final --------
    cudaEventRecord(evJoin, hs);
    cudaStreamWaitEvent(0, evJoin, 0);
    final_k<<<cdiv(NN, 128), 128, 0, 0>>>(SIMPLE, G1, h4b, lpw, lpb, (float*)d_out, NN);
}